// round 1
// baseline (speedup 1.0000x reference)
#include <cuda_runtime.h>
#include <stdint.h>

// ---------------- problem constants ----------------
#define B_    16384
#define DIN   768
#define HD0   512
#define HD1   256
#define HD2   128
#define NQ    4
#define KC    8192
#define EPS_  1e-6f

// ---------------- scratch (device globals; no allocs allowed) ----------------
__device__ float g_xn[B_ * DIN];      // normalized input (needed for recon loss)
__device__ float g_a[B_ * HD0];       // 512-wide stage buffer
__device__ float g_b[B_ * HD1];       // 256-wide stage buffer
__device__ float g_h[B_ * HD2];       // encoder latent
__device__ float g_res[B_ * HD2];     // VQ residual
__device__ float g_qsum[B_ * HD2];    // sum of quantized vectors
__device__ float g_enorm[NQ * KC];    // ||e||^2 per code
__device__ int   g_bestidx[B_];       // per-quantizer argmin result
__device__ float g_vqrow[B_];         // per-row accumulated squared error
__device__ float g_p1[2048];          // recon-loss partials
__device__ float g_p2[64];            // vq-loss partials

// ---------------- small helpers ----------------
__device__ __forceinline__ float blockReduce256(float v) {
    __shared__ float red[32];
    int lane = threadIdx.x & 31, w = threadIdx.x >> 5;
#pragma unroll
    for (int o = 16; o > 0; o >>= 1) v += __shfl_down_sync(0xffffffffu, v, o);
    __syncthreads();
    if (lane == 0) red[w] = v;
    __syncthreads();
    if (threadIdx.x == 0) {
        float t = 0.0f;
        int nw = (blockDim.x + 31) >> 5;
        for (int i = 0; i < nw; i++) t += red[i];
        red[0] = t;
    }
    __syncthreads();
    return red[0];
}

// ---------------- kernels ----------------

// xn = (x - mean) / std
__global__ void k_normalize(const float* __restrict__ x,
                            const float* __restrict__ mean,
                            const float* __restrict__ stdv) {
    int n = B_ * DIN;
    for (int i = blockIdx.x * blockDim.x + threadIdx.x; i < n;
         i += gridDim.x * blockDim.x) {
        int c = i % DIN;
        g_xn[i] = (x[i] - mean[c]) / stdv[c];
    }
}

// C[M,N] = act(A[M,K] @ W[K,N] + bias), M=16384, tile 64x64x16, 4x4 micro-tile
template <bool RELU>
__global__ __launch_bounds__(256)
void k_gemm(const float* __restrict__ A, const float* __restrict__ W,
            const float* __restrict__ bias, float* __restrict__ C,
            int N, int K) {
    __shared__ float As[16][68];  // transposed: As[k][m]
    __shared__ float Ws[16][68];
    int m0 = blockIdx.y * 64, n0 = blockIdx.x * 64;
    int tid = threadIdx.x;
    int ty = tid >> 4, tx = tid & 15;
    int arow = tid >> 2, acol = (tid & 3) * 4;
    int wrow = tid >> 4, wcol = (tid & 15) * 4;

    float acc[4][4] = {};
    for (int k0 = 0; k0 < K; k0 += 16) {
        float4 av = *(const float4*)&A[(size_t)(m0 + arow) * K + k0 + acol];
        As[acol + 0][arow] = av.x;
        As[acol + 1][arow] = av.y;
        As[acol + 2][arow] = av.z;
        As[acol + 3][arow] = av.w;
        *(float4*)&Ws[wrow][wcol] =
            *(const float4*)&W[(size_t)(k0 + wrow) * N + n0 + wcol];
        __syncthreads();
#pragma unroll
        for (int k = 0; k < 16; k++) {
            float4 a4 = *(const float4*)&As[k][ty * 4];
            float4 w4 = *(const float4*)&Ws[k][tx * 4];
            float ar[4] = {a4.x, a4.y, a4.z, a4.w};
            float wr[4] = {w4.x, w4.y, w4.z, w4.w};
#pragma unroll
            for (int i = 0; i < 4; i++)
#pragma unroll
                for (int j = 0; j < 4; j++) acc[i][j] += ar[i] * wr[j];
        }
        __syncthreads();
    }
#pragma unroll
    for (int j = 0; j < 4; j++) {
        float bj = bias[n0 + tx * 4 + j];
#pragma unroll
        for (int i = 0; i < 4; i++) {
            float v = acc[i][j] + bj;
            if (RELU) v = fmaxf(v, 0.0f);
            C[(size_t)(m0 + ty * 4 + i) * N + n0 + tx * 4 + j] = v;
        }
    }
}

// row-wise RMSNorm in place: x *= rsqrt(mean(x^2)+eps) * g
__global__ void k_rmsnorm(float* __restrict__ X, const float* __restrict__ g,
                          int N) {
    int row = blockIdx.x;
    float* xr = X + (size_t)row * N;
    float s = 0.0f;
    for (int n = threadIdx.x; n < N; n += blockDim.x) {
        float v = xr[n];
        s += v * v;
    }
    s = blockReduce256(s);
    float scale = rsqrtf(s / (float)N + EPS_);
    for (int n = threadIdx.x; n < N; n += blockDim.x)
        xr[n] = xr[n] * scale * g[n];
}

// ||e||^2 for all NQ*KC codes
__global__ void k_enorm(const float* __restrict__ cb) {
    int c = blockIdx.x * blockDim.x + threadIdx.x;
    if (c < NQ * KC) {
        const float4* p = (const float4*)(cb + (size_t)c * HD2);
        float s = 0.0f;
#pragma unroll 8
        for (int i = 0; i < HD2 / 4; i++) {
            float4 v = p[i];
            s += v.x * v.x + v.y * v.y + v.z * v.z + v.w * v.w;
        }
        g_enorm[c] = s;
    }
}

__global__ void k_copy_res() {
    int n = B_ * HD2;
    for (int i = blockIdx.x * blockDim.x + threadIdx.x; i < n;
         i += gridDim.x * blockDim.x)
        g_res[i] = g_h[i];
}

// Fused VQ score GEMM + argmin. Block: 64 rows x ALL 8192 codes.
// dist' = ||e||^2 - 2 * (r . e); packed (sortable_bits<<32 | code) running min.
__global__ __launch_bounds__(256)
void k_vq_argmin(const float* __restrict__ cb, const float* __restrict__ en) {
    __shared__ __align__(16) float r_t[128][64];  // 32 KB, swizzled [k][row]
    __shared__ __align__(16) float e_t[64][64];   // 16 KB, swizzled [k][code]
    int tid = threadIdx.x;
    int m0 = blockIdx.x * 64;

    for (int idx = tid; idx < 64 * 128; idx += 256) {
        int row = idx >> 7, k = idx & 127;
        r_t[k][row ^ ((k & 15) << 2)] = g_res[(size_t)(m0 + row) * HD2 + k];
    }

    int ty = tid >> 4, tx = tid & 15;
    unsigned long long best[4] = {~0ULL, ~0ULL, ~0ULL, ~0ULL};

    for (int c0 = 0; c0 < KC; c0 += 64) {
        float acc[4][4] = {};
#pragma unroll
        for (int ks = 0; ks < 2; ks++) {
            __syncthreads();  // protect e_t from readers of previous stage
            for (int idx = tid; idx < 64 * 64; idx += 256) {
                int kk = idx & 63, c = idx >> 6;
                e_t[kk][c ^ ((kk & 15) << 2)] =
                    cb[(size_t)(c0 + c) * HD2 + ks * 64 + kk];
            }
            __syncthreads();
#pragma unroll 16
            for (int kk = 0; kk < 64; kk++) {
                int sw = (kk & 15) << 2;
                float4 a4 = *(const float4*)&r_t[ks * 64 + kk][(ty * 4) ^ sw];
                float4 e4 = *(const float4*)&e_t[kk][(tx * 4) ^ sw];
                float ar[4] = {a4.x, a4.y, a4.z, a4.w};
                float ev[4] = {e4.x, e4.y, e4.z, e4.w};
#pragma unroll
                for (int i = 0; i < 4; i++)
#pragma unroll
                    for (int j = 0; j < 4; j++) acc[i][j] += ar[i] * ev[j];
            }
        }
#pragma unroll
        for (int j = 0; j < 4; j++) {
            int code = c0 + tx * 4 + j;
            float enj = __ldg(&en[code]);
#pragma unroll
            for (int i = 0; i < 4; i++) {
                float d = enj - 2.0f * acc[i][j];
                unsigned u = __float_as_uint(d);
                u ^= ((unsigned)((int)u >> 31)) | 0x80000000u;
                unsigned long long key =
                    ((unsigned long long)u << 32) | (unsigned)code;
                best[i] = min(best[i], key);
            }
        }
    }

    __syncthreads();
    unsigned long long* red = (unsigned long long*)&e_t[0][0];  // 8 KB alias
#pragma unroll
    for (int i = 0; i < 4; i++) red[(ty * 4 + i) * 16 + tx] = best[i];
    __syncthreads();
    if (tid < 64) {
        unsigned long long m = red[tid * 16];
#pragma unroll
        for (int t = 1; t < 16; t++) m = min(m, red[tid * 16 + t]);
        g_bestidx[m0 + tid] = (int)(m & 0xFFFFFFFFu);
    }
}

// gather code, accumulate qsum / vq squared error, update residual, emit id
__global__ void k_vq_update(const float* __restrict__ cb,
                            float* __restrict__ out_ids, int q, int first) {
    int row = blockIdx.x, d = threadIdx.x;  // 128 threads
    int idx = g_bestidx[row];
    float e = cb[(size_t)idx * HD2 + d];
    size_t off = (size_t)row * HD2 + d;
    float r = g_res[off];
    float diff = r - e;
    if (first) g_qsum[off] = e;
    else g_qsum[off] += e;
    g_res[off] = diff;

    __shared__ float s[128];
    s[d] = diff * diff;
    __syncthreads();
#pragma unroll
    for (int o = 64; o > 0; o >>= 1) {
        if (d < o) s[d] += s[d + o];
        __syncthreads();
    }
    if (d == 0) {
        if (first) g_vqrow[row] = s[0];
        else g_vqrow[row] += s[0];
        out_ids[(size_t)row * NQ + q] = (float)idx;
    }
}

__global__ void k_recon_part(const float* __restrict__ recon) {
    float s = 0.0f;
    int n = B_ * DIN;
    for (int i = blockIdx.x * blockDim.x + threadIdx.x; i < n;
         i += gridDim.x * blockDim.x) {
        float d = recon[i] - g_xn[i];
        s += d * d;
    }
    s = blockReduce256(s);
    if (threadIdx.x == 0) g_p1[blockIdx.x] = s;
}

__global__ void k_vq_part() {
    float s = 0.0f;
    for (int i = blockIdx.x * blockDim.x + threadIdx.x; i < B_;
         i += gridDim.x * blockDim.x)
        s += g_vqrow[i];
    s = blockReduce256(s);
    if (threadIdx.x == 0) g_p2[blockIdx.x] = s;
}

__global__ void k_final(float* __restrict__ out) {
    float s1 = 0.0f;
    for (int i = threadIdx.x; i < 2048; i += 256) s1 += g_p1[i];
    s1 = blockReduce256(s1);
    float s2 = 0.0f;
    for (int i = threadIdx.x; i < 64; i += 256) s2 += g_p2[i];
    s2 = blockReduce256(s2);
    if (threadIdx.x == 0) {
        out[0] = s1 / (float)((size_t)B_ * DIN);          // recon_loss
        out[1] = 1.25f * s2 / (float)((size_t)B_ * HD2);  // vq_loss
    }
}

// ---------------- launch ----------------
extern "C" void kernel_launch(void* const* d_in, const int* in_sizes, int n_in,
                              void* d_out, int out_size) {
    const float* x        = (const float*)d_in[0];
    const float* emb_mean = (const float*)d_in[1];
    const float* emb_std  = (const float*)d_in[2];
    const float* enc_w0   = (const float*)d_in[3];
    const float* enc_b0   = (const float*)d_in[4];
    const float* enc_g0   = (const float*)d_in[5];
    const float* enc_w1   = (const float*)d_in[6];
    const float* enc_b1   = (const float*)d_in[7];
    const float* enc_g1   = (const float*)d_in[8];
    const float* enc_w2   = (const float*)d_in[9];
    const float* enc_b2   = (const float*)d_in[10];
    const float* enc_g2   = (const float*)d_in[11];
    const float* cbs      = (const float*)d_in[12];
    const float* dec_w0   = (const float*)d_in[13];
    const float* dec_b0   = (const float*)d_in[14];
    const float* dec_g0   = (const float*)d_in[15];
    const float* dec_w1   = (const float*)d_in[16];
    const float* dec_b1   = (const float*)d_in[17];
    const float* dec_g1   = (const float*)d_in[18];
    const float* dec_w2   = (const float*)d_in[19];
    const float* dec_b2   = (const float*)d_in[20];

    float* out       = (float*)d_out;
    float* out_recon = out;
    float* out_ids   = out + (size_t)B_ * DIN;
    float* out_loss  = out_ids + (size_t)B_ * NQ;

    float *p_xn, *p_a, *p_b, *p_h, *p_qsum, *p_en;
    cudaGetSymbolAddress((void**)&p_xn, g_xn);
    cudaGetSymbolAddress((void**)&p_a, g_a);
    cudaGetSymbolAddress((void**)&p_b, g_b);
    cudaGetSymbolAddress((void**)&p_h, g_h);
    cudaGetSymbolAddress((void**)&p_qsum, g_qsum);
    cudaGetSymbolAddress((void**)&p_en, g_enorm);

    // input normalization
    k_normalize<<<4096, 256>>>(x, emb_mean, emb_std);

    // encoder
    k_gemm<true><<<dim3(HD0 / 64, B_ / 64), 256>>>(p_xn, enc_w0, enc_b0, p_a, HD0, DIN);
    k_rmsnorm<<<B_, 256>>>(p_a, enc_g0, HD0);
    k_gemm<true><<<dim3(HD1 / 64, B_ / 64), 256>>>(p_a, enc_w1, enc_b1, p_b, HD1, HD0);
    k_rmsnorm<<<B_, 256>>>(p_b, enc_g1, HD1);
    k_gemm<true><<<dim3(HD2 / 64, B_ / 64), 256>>>(p_b, enc_w2, enc_b2, p_h, HD2, HD1);
    k_rmsnorm<<<B_, 256>>>(p_h, enc_g2, HD2);

    // residual VQ
    k_enorm<<<(NQ * KC) / 256, 256>>>(cbs);
    k_copy_res<<<2048, 256>>>();
    for (int q = 0; q < NQ; q++) {
        const float* cbq = cbs + (size_t)q * KC * HD2;
        k_vq_argmin<<<B_ / 64, 256>>>(cbq, p_en + (size_t)q * KC);
        k_vq_update<<<B_, 128>>>(cbq, out_ids, q, q == 0 ? 1 : 0);
    }

    // decoder
    k_gemm<true><<<dim3(HD1 / 64, B_ / 64), 256>>>(p_qsum, dec_w0, dec_b0, p_b, HD1, HD2);
    k_rmsnorm<<<B_, 256>>>(p_b, dec_g0, HD1);
    k_gemm<true><<<dim3(HD0 / 64, B_ / 64), 256>>>(p_b, dec_w1, dec_b1, p_a, HD0, HD1);
    k_rmsnorm<<<B_, 256>>>(p_a, dec_g1, HD0);
    k_gemm<false><<<dim3(DIN / 64, B_ / 64), 256>>>(p_a, dec_w2, dec_b2, out_recon, DIN, HD0);

    // losses (deterministic two-stage reductions)
    k_recon_part<<<2048, 256>>>(out_recon);
    k_vq_part<<<64, 256>>>();
    k_final<<<1, 256>>>(out_loss);
}

// round 3
// speedup vs baseline: 1.4924x; 1.4924x over previous
#include <cuda_runtime.h>
#include <cuda_bf16.h>
#include <stdint.h>

// ---------------- problem constants ----------------
#define B_    16384
#define DIN   768
#define HD0   512
#define HD1   256
#define HD2   128
#define NQ    4
#define KC    8192
#define EPS_  1e-6f

// VQ tensor-core geometry (HMMA mma.sync path)
#define KP      384               // 3*128: [hi|hi|lo] x [ehi|elo|ehi]
#define TILE_N  64
#define NTILES  (KC / TILE_N)     // 128
#define SMEM_A_BYTES (128 * KP * 2)   // 98304
#define SMEM_B_BYTES (TILE_N * KP * 2) // 49152
#define SMEM_VQ (SMEM_A_BYTES + 2 * SMEM_B_BYTES)  // 196608
#define VQ_MARGIN 4e-4f

// ---------------- scratch ----------------
__device__ float g_xn[B_ * DIN];
__device__ float g_a[B_ * HD0];
__device__ float g_b[B_ * HD1];
__device__ float g_h[B_ * HD2];
__device__ float g_res[B_ * HD2];
__device__ float g_qsum[B_ * HD2];
__device__ float g_enorm[NQ * KC];
__device__ int   g_bestidx[B_];
__device__ int   g_flag[B_];
__device__ float g_vqrow[B_];
__device__ float g_p1[2048];
__device__ float g_p2[64];
__device__ __nv_bfloat16 g_resA[B_ * KP];        // A' rows (plain row-major)
__device__ __nv_bfloat16 g_cbB[NQ * KC * KP];    // B' rows (plain row-major)

// ---------------- PTX helpers (sm_80-era, safe on compute_103) ----------------
__device__ __forceinline__ uint32_t smem_u32(const void* p) {
    uint32_t a;
    asm("{ .reg .u64 t; cvta.to.shared.u64 t, %1; cvt.u32.u64 %0, t; }" : "=r"(a) : "l"(p));
    return a;
}
#define CP_ASYNC16(dst, src) \
    asm volatile("cp.async.cg.shared.global [%0], [%1], 16;" :: "r"(dst), "l"(src))
#define CP_COMMIT() asm volatile("cp.async.commit_group;" ::: "memory")
#define CP_WAIT0()  asm volatile("cp.async.wait_group 0;" ::: "memory")
#define CP_WAIT1()  asm volatile("cp.async.wait_group 1;" ::: "memory")

__device__ __forceinline__ void ldsm_x4(uint32_t* r, uint32_t addr) {
    asm volatile("ldmatrix.sync.aligned.m8n8.x4.shared.b16 {%0,%1,%2,%3}, [%4];"
                 : "=r"(r[0]), "=r"(r[1]), "=r"(r[2]), "=r"(r[3]) : "r"(addr));
}
__device__ __forceinline__ void mma16816(float* c, const uint32_t* a, const uint32_t* b) {
    asm volatile(
        "mma.sync.aligned.m16n8k16.row.col.f32.bf16.bf16.f32 "
        "{%0,%1,%2,%3}, {%4,%5,%6,%7}, {%8,%9}, {%0,%1,%2,%3};"
        : "+f"(c[0]), "+f"(c[1]), "+f"(c[2]), "+f"(c[3])
        : "r"(a[0]), "r"(a[1]), "r"(a[2]), "r"(a[3]), "r"(b[0]), "r"(b[1]));
}

__device__ __forceinline__ unsigned f2ord(float f) {
    unsigned u = __float_as_uint(f);
    return u ^ (((unsigned)((int)u >> 31)) | 0x80000000u);
}
__device__ __forceinline__ float ord2f(unsigned u) {
    u ^= (u & 0x80000000u) ? 0x80000000u : 0xFFFFFFFFu;
    return __uint_as_float(u);
}

// ---------------- small helpers ----------------
__device__ __forceinline__ float blockReduce256(float v) {
    __shared__ float red[32];
    int lane = threadIdx.x & 31, w = threadIdx.x >> 5;
#pragma unroll
    for (int o = 16; o > 0; o >>= 1) v += __shfl_down_sync(0xffffffffu, v, o);
    __syncthreads();
    if (lane == 0) red[w] = v;
    __syncthreads();
    if (threadIdx.x == 0) {
        float t = 0.0f;
        int nw = (blockDim.x + 31) >> 5;
        for (int i = 0; i < nw; i++) t += red[i];
        red[0] = t;
    }
    __syncthreads();
    return red[0];
}

// ---------------- elementwise / MLP kernels (R1, proven) ----------------
__global__ void k_normalize(const float* __restrict__ x,
                            const float* __restrict__ mean,
                            const float* __restrict__ stdv) {
    int n = B_ * DIN;
    for (int i = blockIdx.x * blockDim.x + threadIdx.x; i < n;
         i += gridDim.x * blockDim.x) {
        int c = i % DIN;
        g_xn[i] = (x[i] - mean[c]) / stdv[c];
    }
}

template <bool RELU>
__global__ __launch_bounds__(256)
void k_gemm(const float* __restrict__ A, const float* __restrict__ W,
            const float* __restrict__ bias, float* __restrict__ C,
            int N, int K) {
    __shared__ float As[16][68];
    __shared__ float Ws[16][68];
    int m0 = blockIdx.y * 64, n0 = blockIdx.x * 64;
    int tid = threadIdx.x;
    int ty = tid >> 4, tx = tid & 15;
    int arow = tid >> 2, acol = (tid & 3) * 4;
    int wrow = tid >> 4, wcol = (tid & 15) * 4;

    float acc[4][4] = {};
    for (int k0 = 0; k0 < K; k0 += 16) {
        float4 av = *(const float4*)&A[(size_t)(m0 + arow) * K + k0 + acol];
        As[acol + 0][arow] = av.x;
        As[acol + 1][arow] = av.y;
        As[acol + 2][arow] = av.z;
        As[acol + 3][arow] = av.w;
        *(float4*)&Ws[wrow][wcol] =
            *(const float4*)&W[(size_t)(k0 + wrow) * N + n0 + wcol];
        __syncthreads();
#pragma unroll
        for (int k = 0; k < 16; k++) {
            float4 a4 = *(const float4*)&As[k][ty * 4];
            float4 w4 = *(const float4*)&Ws[k][tx * 4];
            float ar[4] = {a4.x, a4.y, a4.z, a4.w};
            float wr[4] = {w4.x, w4.y, w4.z, w4.w};
#pragma unroll
            for (int i = 0; i < 4; i++)
#pragma unroll
                for (int j = 0; j < 4; j++) acc[i][j] += ar[i] * wr[j];
        }
        __syncthreads();
    }
#pragma unroll
    for (int j = 0; j < 4; j++) {
        float bj = bias[n0 + tx * 4 + j];
#pragma unroll
        for (int i = 0; i < 4; i++) {
            float v = acc[i][j] + bj;
            if (RELU) v = fmaxf(v, 0.0f);
            C[(size_t)(m0 + ty * 4 + i) * N + n0 + tx * 4 + j] = v;
        }
    }
}

__global__ void k_rmsnorm(float* __restrict__ X, const float* __restrict__ g, int N) {
    int row = blockIdx.x;
    float* xr = X + (size_t)row * N;
    float s = 0.0f;
    for (int n = threadIdx.x; n < N; n += blockDim.x) {
        float v = xr[n];
        s += v * v;
    }
    s = blockReduce256(s);
    float scale = rsqrtf(s / (float)N + EPS_);
    for (int n = threadIdx.x; n < N; n += blockDim.x)
        xr[n] = xr[n] * scale * g[n];
}

__global__ void k_enorm(const float* __restrict__ cb) {
    int c = blockIdx.x * blockDim.x + threadIdx.x;
    if (c < NQ * KC) {
        const float4* p = (const float4*)(cb + (size_t)c * HD2);
        float s = 0.0f;
#pragma unroll 8
        for (int i = 0; i < HD2 / 4; i++) {
            float4 v = p[i];
            s += v.x * v.x + v.y * v.y + v.z * v.z + v.w * v.w;
        }
        g_enorm[c] = s;
    }
}

__global__ void k_copy_res() {
    int n = B_ * HD2;
    for (int i = blockIdx.x * blockDim.x + threadIdx.x; i < n;
         i += gridDim.x * blockDim.x)
        g_res[i] = g_h[i];
}

// ---------------- VQ prep: bf16 hi/lo expanded rows ----------------
__global__ void k_prepA() {
    int idx = blockIdx.x * blockDim.x + threadIdx.x;
    if (idx >= B_ * KP) return;
    int row = idx / KP, kp = idx - row * KP;
    float x = g_res[row * HD2 + (kp & 127)];
    __nv_bfloat16 hi = __float2bfloat16(x);
    g_resA[idx] = (kp < 256) ? hi : __float2bfloat16(x - __bfloat162float(hi));
}

__global__ void k_prepB(const float* __restrict__ cb) {
    int idx = blockIdx.x * blockDim.x + threadIdx.x;
    if (idx >= NQ * KC * KP) return;
    int kp = idx % KP;
    int qc = idx / KP;  // q*KC + code
    float x = cb[(size_t)qc * HD2 + (kp & 127)];
    __nv_bfloat16 hi = __float2bfloat16(x);
    // B' order: [ehi | elo | ehi] to pair with A' [hi | hi | lo]
    g_cbB[idx] = (kp >= 128 && kp < 256)
                 ? __float2bfloat16(x - __bfloat162float(hi)) : hi;
}

// ---------------- fused VQ score GEMM + argmin (HMMA) ----------------
// CTA: 256 thr, 128 rows x all 8192 codes. A resident (96KB), B double-buffered.
__global__ __launch_bounds__(256, 1)
void k_vq_mma(const __nv_bfloat16* __restrict__ Ablk,
              const __nv_bfloat16* __restrict__ Bq,
              const float* __restrict__ en) {
    extern __shared__ char smem[];
    uint32_t sA = smem_u32(smem);
    uint32_t sB0 = sA + SMEM_A_BYTES;
    __shared__ unsigned long long skey[2][128];
    __shared__ float ssec[2][128];

    int tid = threadIdx.x, lid = tid & 31, wid = tid >> 5;
    int wm = wid & 3, wn = wid >> 2;     // warp grid 4(m) x 2(n)
    int tg = lid & 3, g = lid >> 2;
    int grp = lid >> 3, sub = lid & 7;

    // stage A block (swizzled quads: quad(m,k8) at m*768 + ((k8 ^ (m&7))<<4))
    const char* gA = (const char*)(Ablk + (size_t)blockIdx.x * 128 * KP);
    for (int i = tid; i < 6144; i += 256) {
        int m = i / 48, k8 = i % 48;
        CP_ASYNC16(sA + m * 768 + ((k8 ^ (m & 7)) << 4), gA + i * 16);
    }
    // prefetch B tile 0
    {
        const char* gB = (const char*)Bq;
        for (int i = tid; i < 3072; i += 256) {
            int n = i / 48, k8 = i % 48;
            CP_ASYNC16(sB0 + n * 768 + ((k8 ^ (n & 7)) << 4), gB + i * 16);
        }
    }
    CP_COMMIT();

    // ldmatrix lane-address invariants
    uint32_t aBase[2]; int aXor[2], aG2 = grp >> 1;
#pragma unroll
    for (int mc = 0; mc < 2; mc++) {
        int row = wm * 32 + mc * 16 + (grp & 1) * 8 + sub;
        aBase[mc] = sA + row * 768;
        aXor[mc] = row & 7;
    }
    uint32_t bOff[2]; int bXor[2], bK8b = grp & 1;
#pragma unroll
    for (int p = 0; p < 2; p++) {
        int n = wn * 32 + p * 16 + (grp >> 1) * 8 + sub;
        bOff[p] = n * 768;
        bXor[p] = n & 7;
    }

    float bd[4] = {1e30f, 1e30f, 1e30f, 1e30f};
    float sd[4] = {1e30f, 1e30f, 1e30f, 1e30f};
    int bc[4] = {0, 0, 0, 0};

    for (int t = 0; t < NTILES; t++) {
        if (t + 1 < NTILES) {
            const char* gB = (const char*)(Bq + (size_t)(t + 1) * TILE_N * KP);
            uint32_t sBn = sB0 + ((t + 1) & 1) * SMEM_B_BYTES;
            for (int i = tid; i < 3072; i += 256) {
                int n = i / 48, k8 = i % 48;
                CP_ASYNC16(sBn + n * 768 + ((k8 ^ (n & 7)) << 4), gB + i * 16);
            }
            CP_COMMIT();
            CP_WAIT1();
        } else {
            CP_WAIT0();
        }
        __syncthreads();

        uint32_t sBt = sB0 + (t & 1) * SMEM_B_BYTES;
        float acc[2][4][4] = {};
#pragma unroll
        for (int ks = 0; ks < 24; ks++) {
            uint32_t aF[2][4], bF[2][4];
#pragma unroll
            for (int mc = 0; mc < 2; mc++)
                ldsm_x4(aF[mc], aBase[mc] + ((((ks * 2 + aG2) ^ aXor[mc])) << 4));
#pragma unroll
            for (int p = 0; p < 2; p++)
                ldsm_x4(bF[p], sBt + bOff[p] + ((((ks * 2 + bK8b) ^ bXor[p])) << 4));
#pragma unroll
            for (int mc = 0; mc < 2; mc++)
#pragma unroll
                for (int c = 0; c < 4; c++)
                    mma16816(acc[mc][c], aF[mc], &bF[c >> 1][(c & 1) * 2]);
        }

        // epilogue: distances + best/second tracking (register only)
        int colbase = t * TILE_N + wn * 32;
#pragma unroll
        for (int c = 0; c < 4; c++) {
            int col0 = colbase + c * 8 + tg * 2;
            float e0 = __ldg(en + col0), e1 = __ldg(en + col0 + 1);
#pragma unroll
            for (int mc = 0; mc < 2; mc++) {
                float d0 = fmaf(-2.0f, acc[mc][c][0], e0);
                float d1 = fmaf(-2.0f, acc[mc][c][1], e1);
                float d2 = fmaf(-2.0f, acc[mc][c][2], e0);
                float d3 = fmaf(-2.0f, acc[mc][c][3], e1);
                int s0 = mc * 2, s1 = mc * 2 + 1;
                if (d0 < bd[s0]) { sd[s0] = bd[s0]; bd[s0] = d0; bc[s0] = col0; }
                else if (d0 < sd[s0]) sd[s0] = d0;
                if (d1 < bd[s0]) { sd[s0] = bd[s0]; bd[s0] = d1; bc[s0] = col0 + 1; }
                else if (d1 < sd[s0]) sd[s0] = d1;
                if (d2 < bd[s1]) { sd[s1] = bd[s1]; bd[s1] = d2; bc[s1] = col0; }
                else if (d2 < sd[s1]) sd[s1] = d2;
                if (d3 < bd[s1]) { sd[s1] = bd[s1]; bd[s1] = d3; bc[s1] = col0 + 1; }
                else if (d3 < sd[s1]) sd[s1] = d3;
            }
        }
        __syncthreads();
    }

    // merge across the 4 lanes (tg) sharing each row
#pragma unroll
    for (int s = 0; s < 4; s++) {
        unsigned long long key =
            ((unsigned long long)f2ord(bd[s]) << 32) | (unsigned)bc[s];
        float bf = bd[s], sf = sd[s];
#pragma unroll
        for (int off = 1; off <= 2; off <<= 1) {
            unsigned long long ok = __shfl_xor_sync(0xffffffffu, key, off);
            float os = __shfl_xor_sync(0xffffffffu, sf, off);
            float ob = ord2f((unsigned)(ok >> 32));
            sf = fminf(fmaxf(bf, ob), fminf(sf, os));
            bf = fminf(bf, ob);
            if (ok < key) key = ok;
        }
        if (tg == 0) {
            int row = wm * 32 + (s >> 1) * 16 + (s & 1) * 8 + g;
            skey[wn][row] = key;
            ssec[wn][row] = sf;
        }
    }
    __syncthreads();
    if (tid < 128) {
        unsigned long long k0 = skey[0][tid], k1 = skey[1][tid];
        float b0 = ord2f((unsigned)(k0 >> 32)), b1 = ord2f((unsigned)(k1 >> 32));
        float sec = fminf(fmaxf(b0, b1), fminf(ssec[0][tid], ssec[1][tid]));
        unsigned long long km = min(k0, k1);
        float best = ord2f((unsigned)(km >> 32));
        int row = blockIdx.x * 128 + tid;
        g_bestidx[row] = (int)(km & 0xFFFFFFFFu);
        g_flag[row] = (sec - best) < VQ_MARGIN ? 1 : 0;
    }
}

// exact fp32 re-scan for margin-flagged rows (rare)
__global__ void k_vq_exact(const float* __restrict__ cb, const float* __restrict__ en) {
    int row = blockIdx.x;
    if (!g_flag[row]) return;
    __shared__ float r[HD2];
    __shared__ unsigned long long red[128];
    int t = threadIdx.x;
    if (t < HD2) r[t] = g_res[(size_t)row * HD2 + t];
    __syncthreads();
    unsigned long long best = ~0ULL;
    for (int c = t; c < KC; c += 128) {
        const float4* e4 = (const float4*)(cb + (size_t)c * HD2);
        float dot = 0.0f;
#pragma unroll 8
        for (int i = 0; i < HD2 / 4; i++) {
            float4 v = e4[i];
            dot += r[4 * i] * v.x + r[4 * i + 1] * v.y + r[4 * i + 2] * v.z + r[4 * i + 3] * v.w;
        }
        float d = en[c] - 2.0f * dot;
        unsigned long long key = ((unsigned long long)f2ord(d) << 32) | (unsigned)c;
        best = min(best, key);
    }
    red[t] = best;
    __syncthreads();
#pragma unroll
    for (int o = 64; o > 0; o >>= 1) {
        if (t < o) red[t] = min(red[t], red[t + o]);
        __syncthreads();
    }
    if (t == 0) g_bestidx[row] = (int)(red[0] & 0xFFFFFFFFu);
}

__global__ void k_vq_update(const float* __restrict__ cb,
                            float* __restrict__ out_ids, int q, int first) {
    int row = blockIdx.x, d = threadIdx.x;
    int idx = g_bestidx[row];
    float e = cb[(size_t)idx * HD2 + d];
    size_t off = (size_t)row * HD2 + d;
    float r = g_res[off];
    float diff = r - e;
    if (first) g_qsum[off] = e;
    else g_qsum[off] += e;
    g_res[off] = diff;

    __shared__ float s[128];
    s[d] = diff * diff;
    __syncthreads();
#pragma unroll
    for (int o = 64; o > 0; o >>= 1) {
        if (d < o) s[d] += s[d + o];
        __syncthreads();
    }
    if (d == 0) {
        if (first) g_vqrow[row] = s[0];
        else g_vqrow[row] += s[0];
        out_ids[(size_t)row * NQ + q] = (float)idx;
    }
}

__global__ void k_recon_part(const float* __restrict__ recon) {
    float s = 0.0f;
    int n = B_ * DIN;
    for (int i = blockIdx.x * blockDim.x + threadIdx.x; i < n;
         i += gridDim.x * blockDim.x) {
        float d = recon[i] - g_xn[i];
        s += d * d;
    }
    s = blockReduce256(s);
    if (threadIdx.x == 0) g_p1[blockIdx.x] = s;
}

__global__ void k_vq_part() {
    float s = 0.0f;
    for (int i = blockIdx.x * blockDim.x + threadIdx.x; i < B_;
         i += gridDim.x * blockDim.x)
        s += g_vqrow[i];
    s = blockReduce256(s);
    if (threadIdx.x == 0) g_p2[blockIdx.x] = s;
}

__global__ void k_final(float* __restrict__ out) {
    float s1 = 0.0f;
    for (int i = threadIdx.x; i < 2048; i += 256) s1 += g_p1[i];
    s1 = blockReduce256(s1);
    float s2 = 0.0f;
    for (int i = threadIdx.x; i < 64; i += 256) s2 += g_p2[i];
    s2 = blockReduce256(s2);
    if (threadIdx.x == 0) {
        out[0] = s1 / (float)((size_t)B_ * DIN);
        out[1] = 1.25f * s2 / (float)((size_t)B_ * HD2);
    }
}

// ---------------- launch ----------------
extern "C" void kernel_launch(void* const* d_in, const int* in_sizes, int n_in,
                              void* d_out, int out_size) {
    const float* x        = (const float*)d_in[0];
    const float* emb_mean = (const float*)d_in[1];
    const float* emb_std  = (const float*)d_in[2];
    const float* enc_w0   = (const float*)d_in[3];
    const float* enc_b0   = (const float*)d_in[4];
    const float* enc_g0   = (const float*)d_in[5];
    const float* enc_w1   = (const float*)d_in[6];
    const float* enc_b1   = (const float*)d_in[7];
    const float* enc_g1   = (const float*)d_in[8];
    const float* enc_w2   = (const float*)d_in[9];
    const float* enc_b2   = (const float*)d_in[10];
    const float* enc_g2   = (const float*)d_in[11];
    const float* cbs      = (const float*)d_in[12];
    const float* dec_w0   = (const float*)d_in[13];
    const float* dec_b0   = (const float*)d_in[14];
    const float* dec_g0   = (const float*)d_in[15];
    const float* dec_w1   = (const float*)d_in[16];
    const float* dec_b1   = (const float*)d_in[17];
    const float* dec_g1   = (const float*)d_in[18];
    const float* dec_w2   = (const float*)d_in[19];
    const float* dec_b2   = (const float*)d_in[20];

    float* out       = (float*)d_out;
    float* out_recon = out;
    float* out_ids   = out + (size_t)B_ * DIN;
    float* out_loss  = out_ids + (size_t)B_ * NQ;

    cudaFuncSetAttribute(k_vq_mma, cudaFuncAttributeMaxDynamicSharedMemorySize,
                         SMEM_VQ);

    float *p_xn, *p_a, *p_b, *p_h, *p_qsum, *p_en, *pf_resA, *pf_cbB;
    cudaGetSymbolAddress((void**)&p_xn, g_xn);
    cudaGetSymbolAddress((void**)&p_a, g_a);
    cudaGetSymbolAddress((void**)&p_b, g_b);
    cudaGetSymbolAddress((void**)&p_h, g_h);
    cudaGetSymbolAddress((void**)&p_qsum, g_qsum);
    cudaGetSymbolAddress((void**)&p_en, g_enorm);
    cudaGetSymbolAddress((void**)&pf_resA, g_resA);
    cudaGetSymbolAddress((void**)&pf_cbB, g_cbB);
    const __nv_bfloat16* p_resA = (const __nv_bfloat16*)pf_resA;
    const __nv_bfloat16* p_cbB  = (const __nv_bfloat16*)pf_cbB;

    k_normalize<<<4096, 256>>>(x, emb_mean, emb_std);

    // codebook prep (independent of encoder)
    k_enorm<<<(NQ * KC) / 256, 256>>>(cbs);
    k_prepB<<<(NQ * KC * KP + 255) / 256, 256>>>(cbs);

    // encoder
    k_gemm<true><<<dim3(HD0 / 64, B_ / 64), 256>>>(p_xn, enc_w0, enc_b0, p_a, HD0, DIN);
    k_rmsnorm<<<B_, 256>>>(p_a, enc_g0, HD0);
    k_gemm<true><<<dim3(HD1 / 64, B_ / 64), 256>>>(p_a, enc_w1, enc_b1, p_b, HD1, HD0);
    k_rmsnorm<<<B_, 256>>>(p_b, enc_g1, HD1);
    k_gemm<true><<<dim3(HD2 / 64, B_ / 64), 256>>>(p_b, enc_w2, enc_b2, p_h, HD2, HD1);
    k_rmsnorm<<<B_, 256>>>(p_h, enc_g2, HD2);

    // residual VQ (tensor cores via mma.sync)
    k_copy_res<<<2048, 256>>>();
    for (int q = 0; q < NQ; q++) {
        const float* cbq = cbs + (size_t)q * KC * HD2;
        k_prepA<<<(B_ * KP + 255) / 256, 256>>>();
        k_vq_mma<<<B_ / 128, 256, SMEM_VQ>>>(p_resA, p_cbB + (size_t)q * KC * KP,
                                             p_en + (size_t)q * KC);
        k_vq_exact<<<B_, 128>>>(cbq, p_en + (size_t)q * KC);
        k_vq_update<<<B_, 128>>>(cbq, out_ids, q, q == 0 ? 1 : 0);
    }

    // decoder
    k_gemm<true><<<dim3(HD1 / 64, B_ / 64), 256>>>(p_qsum, dec_w0, dec_b0, p_b, HD1, HD2);
    k_rmsnorm<<<B_, 256>>>(p_b, dec_g0, HD1);
    k_gemm<true><<<dim3(HD0 / 64, B_ / 64), 256>>>(p_b, dec_w1, dec_b1, p_a, HD0, HD1);
    k_rmsnorm<<<B_, 256>>>(p_a, dec_g1, HD0);
    k_gemm<false><<<dim3(DIN / 64, B_ / 64), 256>>>(p_a, dec_w2, dec_b2, out_recon, DIN, HD0);

    k_recon_part<<<2048, 256>>>(out_recon);
    k_vq_part<<<64, 256>>>();
    k_final<<<1, 256>>>(out_loss);
}

// round 4
// speedup vs baseline: 1.5374x; 1.0302x over previous
#include <cuda_runtime.h>
#include <cuda_bf16.h>
#include <cuda_fp16.h>
#include <stdint.h>

// ---------------- problem constants ----------------
#define B_    16384
#define DIN   768
#define HD0   512
#define HD1   256
#define HD2   128
#define NQ    4
#define KC    8192
#define EPS_  1e-6f

// VQ tensor-core geometry (fp16 2-term: A'=[hi|lo] K'=256, B'=e_hi K=128)
#define TILE_N  128
#define NTILES  (KC / TILE_N)               // 64
#define A_BLK_ELEMS (128 * 256)             // 32768 halves = 64KB
#define B_TILE_ELEMS (TILE_N * 128)         // 16384 halves = 32KB
#define SMEM_A_BYTES 65536
#define SMEM_B_BYTES 32768
#define SMEM_VQ (SMEM_A_BYTES + 2 * SMEM_B_BYTES)  // 131072
#define VQ_MARGIN 2e-3f

// ---------------- scratch ----------------
__device__ float g_xn[B_ * DIN];
__device__ float g_a[B_ * HD0];
__device__ float g_b[B_ * HD1];
__device__ float g_h[B_ * HD2];
__device__ float g_res[B_ * HD2];
__device__ float g_qsum[B_ * HD2];
__device__ float g_enorm[NQ * KC];
__device__ int   g_bestidx[B_];
__device__ int   g_flag[B_];
__device__ float g_vqrow[B_];
__device__ float g_p1[2048];
__device__ float g_p2[64];
__device__ __half g_resA[B_ * 256];        // A' blocks, pre-swizzled
__device__ __half g_cbB[NQ * KC * 128];    // B' tiles, pre-swizzled

// ---------------- PTX helpers ----------------
__device__ __forceinline__ uint32_t smem_u32(const void* p) {
    uint32_t a;
    asm("{ .reg .u64 t; cvta.to.shared.u64 t, %1; cvt.u32.u64 %0, t; }" : "=r"(a) : "l"(p));
    return a;
}
#define CP_ASYNC16(dst, src) \
    asm volatile("cp.async.cg.shared.global [%0], [%1], 16;" :: "r"(dst), "l"(src))
#define CP_COMMIT() asm volatile("cp.async.commit_group;" ::: "memory")
#define CP_WAIT0()  asm volatile("cp.async.wait_group 0;" ::: "memory")
#define CP_WAIT1()  asm volatile("cp.async.wait_group 1;" ::: "memory")

__device__ __forceinline__ void ldsm_x4(uint32_t* r, uint32_t addr) {
    asm volatile("ldmatrix.sync.aligned.m8n8.x4.shared.b16 {%0,%1,%2,%3}, [%4];"
                 : "=r"(r[0]), "=r"(r[1]), "=r"(r[2]), "=r"(r[3]) : "r"(addr));
}
__device__ __forceinline__ void mma16816h(float* c, const uint32_t* a, const uint32_t* b) {
    asm volatile(
        "mma.sync.aligned.m16n8k16.row.col.f32.f16.f16.f32 "
        "{%0,%1,%2,%3}, {%4,%5,%6,%7}, {%8,%9}, {%0,%1,%2,%3};"
        : "+f"(c[0]), "+f"(c[1]), "+f"(c[2]), "+f"(c[3])
        : "r"(a[0]), "r"(a[1]), "r"(a[2]), "r"(a[3]), "r"(b[0]), "r"(b[1]));
}

__device__ __forceinline__ unsigned f2ord(float f) {
    unsigned u = __float_as_uint(f);
    return u ^ (((unsigned)((int)u >> 31)) | 0x80000000u);
}
__device__ __forceinline__ float ord2f(unsigned u) {
    u ^= (u & 0x80000000u) ? 0x80000000u : 0xFFFFFFFFu;
    return __uint_as_float(u);
}

// ---------------- small helpers ----------------
__device__ __forceinline__ float blockReduce256(float v) {
    __shared__ float red[32];
    int lane = threadIdx.x & 31, w = threadIdx.x >> 5;
#pragma unroll
    for (int o = 16; o > 0; o >>= 1) v += __shfl_down_sync(0xffffffffu, v, o);
    __syncthreads();
    if (lane == 0) red[w] = v;
    __syncthreads();
    if (threadIdx.x == 0) {
        float t = 0.0f;
        int nw = (blockDim.x + 31) >> 5;
        for (int i = 0; i < nw; i++) t += red[i];
        red[0] = t;
    }
    __syncthreads();
    return red[0];
}

// ---------------- elementwise / MLP kernels (proven) ----------------
__global__ void k_normalize(const float* __restrict__ x,
                            const float* __restrict__ mean,
                            const float* __restrict__ stdv) {
    int n = B_ * DIN;
    for (int i = blockIdx.x * blockDim.x + threadIdx.x; i < n;
         i += gridDim.x * blockDim.x) {
        int c = i % DIN;
        g_xn[i] = (x[i] - mean[c]) / stdv[c];
    }
}

template <bool RELU>
__global__ __launch_bounds__(256)
void k_gemm(const float* __restrict__ A, const float* __restrict__ W,
            const float* __restrict__ bias, float* __restrict__ C,
            int N, int K) {
    __shared__ float As[16][68];
    __shared__ float Ws[16][68];
    int m0 = blockIdx.y * 64, n0 = blockIdx.x * 64;
    int tid = threadIdx.x;
    int ty = tid >> 4, tx = tid & 15;
    int arow = tid >> 2, acol = (tid & 3) * 4;
    int wrow = tid >> 4, wcol = (tid & 15) * 4;

    float acc[4][4] = {};
    for (int k0 = 0; k0 < K; k0 += 16) {
        float4 av = *(const float4*)&A[(size_t)(m0 + arow) * K + k0 + acol];
        As[acol + 0][arow] = av.x;
        As[acol + 1][arow] = av.y;
        As[acol + 2][arow] = av.z;
        As[acol + 3][arow] = av.w;
        *(float4*)&Ws[wrow][wcol] =
            *(const float4*)&W[(size_t)(k0 + wrow) * N + n0 + wcol];
        __syncthreads();
#pragma unroll
        for (int k = 0; k < 16; k++) {
            float4 a4 = *(const float4*)&As[k][ty * 4];
            float4 w4 = *(const float4*)&Ws[k][tx * 4];
            float ar[4] = {a4.x, a4.y, a4.z, a4.w};
            float wr[4] = {w4.x, w4.y, w4.z, w4.w};
#pragma unroll
            for (int i = 0; i < 4; i++)
#pragma unroll
                for (int j = 0; j < 4; j++) acc[i][j] += ar[i] * wr[j];
        }
        __syncthreads();
    }
#pragma unroll
    for (int j = 0; j < 4; j++) {
        float bj = bias[n0 + tx * 4 + j];
#pragma unroll
        for (int i = 0; i < 4; i++) {
            float v = acc[i][j] + bj;
            if (RELU) v = fmaxf(v, 0.0f);
            C[(size_t)(m0 + ty * 4 + i) * N + n0 + tx * 4 + j] = v;
        }
    }
}

__global__ void k_rmsnorm(float* __restrict__ X, const float* __restrict__ g, int N) {
    int row = blockIdx.x;
    float* xr = X + (size_t)row * N;
    float s = 0.0f;
    for (int n = threadIdx.x; n < N; n += blockDim.x) {
        float v = xr[n];
        s += v * v;
    }
    s = blockReduce256(s);
    float scale = rsqrtf(s / (float)N + EPS_);
    for (int n = threadIdx.x; n < N; n += blockDim.x)
        xr[n] = xr[n] * scale * g[n];
}

__global__ void k_enorm(const float* __restrict__ cb) {
    int c = blockIdx.x * blockDim.x + threadIdx.x;
    if (c < NQ * KC) {
        const float4* p = (const float4*)(cb + (size_t)c * HD2);
        float s = 0.0f;
#pragma unroll 8
        for (int i = 0; i < HD2 / 4; i++) {
            float4 v = p[i];
            s += v.x * v.x + v.y * v.y + v.z * v.z + v.w * v.w;
        }
        g_enorm[c] = s;
    }
}

__global__ void k_copy_res() {
    int n = B_ * HD2;
    for (int i = blockIdx.x * blockDim.x + threadIdx.x; i < n;
         i += gridDim.x * blockDim.x)
        g_res[i] = g_h[i];
}

// ---------------- VQ prep: fp16 hi/lo, pre-swizzled ----------------
// A' block (128 rows x 256 k'): row m stride 512B; quad k8 at ((k8^(m&7))<<4)
__global__ void k_prepA() {
    int idx = blockIdx.x * blockDim.x + threadIdx.x;
    if (idx >= B_ * 256) return;
    int row = idx >> 8, kp = idx & 255;
    float x = g_res[row * HD2 + (kp & 127)];
    __half hi = __float2half(x);
    __half v = (kp < 128) ? hi : __float2half(x - __half2float(hi));
    int m = row & 127, rb = row >> 7;
    int byte = m * 512 + ((((kp >> 3) ^ (m & 7))) << 4) + (kp & 7) * 2;
    g_resA[rb * A_BLK_ELEMS + (byte >> 1)] = v;
}

// B' tile (128 codes x 128 k): code n stride 256B; quad k8 at ((k8^(n&7))<<4)
__global__ void k_prepB(const float* __restrict__ cb) {
    int idx = blockIdx.x * blockDim.x + threadIdx.x;
    if (idx >= NQ * KC * 128) return;
    int k = idx & 127;
    int qc = idx >> 7;
    int c = qc & (KC - 1), q = qc >> 13;
    __half v = __float2half(cb[(size_t)qc * HD2 + k]);
    int tile = c >> 7, n = c & 127;
    int byte = n * 256 + ((((k >> 3) ^ (n & 7))) << 4) + (k & 7) * 2;
    g_cbB[(size_t)q * (KC * 128) + tile * B_TILE_ELEMS + (byte >> 1)] = v;
}

// ---------------- fused VQ score GEMM + argmin (fp16 HMMA, 512 thr) ----------------
// CTA: 16 warps (4m x 4n), 128 rows x all 8192 codes, 64 tiles of 128 codes.
__global__ __launch_bounds__(512, 1)
void k_vq_mma(const __half* __restrict__ Ablk,
              const __half* __restrict__ Bq,
              const float* __restrict__ en) {
    extern __shared__ char smem[];
    uint32_t sA = smem_u32(smem);
    uint32_t sB0 = sA + SMEM_A_BYTES;
    __shared__ unsigned long long skey[4][128];
    __shared__ float ssec[4][128];

    int tid = threadIdx.x, lid = tid & 31, wid = tid >> 5;
    int wm = wid & 3, wn = wid >> 2;     // warp grid 4(m) x 4(n)
    int tg = lid & 3, g = lid >> 2;
    int grp = lid >> 3, sub = lid & 7;

    // stage A block (identity copy; global layout already swizzled)
    const char* gA = (const char*)(Ablk + (size_t)blockIdx.x * A_BLK_ELEMS);
    for (int i = tid; i < 4096; i += 512)
        CP_ASYNC16(sA + i * 16, gA + i * 16);
    // prefetch B tile 0
    {
        const char* gB = (const char*)Bq;
        for (int i = tid; i < 2048; i += 512)
            CP_ASYNC16(sB0 + i * 16, gB + i * 16);
    }
    CP_COMMIT();

    // ldmatrix lane-address invariants (R3-proven conventions)
    uint32_t aBase[2]; int aXor[2];
    int aG2 = grp >> 1;
#pragma unroll
    for (int mc = 0; mc < 2; mc++) {
        int row = wm * 32 + mc * 16 + (grp & 1) * 8 + sub;
        aBase[mc] = sA + row * 512;
        aXor[mc] = row & 7;
    }
    uint32_t bOff[2]; int bXor[2];
    int bK8b = grp & 1;
#pragma unroll
    for (int p = 0; p < 2; p++) {
        int n = wn * 32 + p * 16 + (grp >> 1) * 8 + sub;
        bOff[p] = n * 256;
        bXor[p] = n & 7;
    }

    float bd[4] = {1e30f, 1e30f, 1e30f, 1e30f};
    float sd[4] = {1e30f, 1e30f, 1e30f, 1e30f};
    int bc[4] = {0, 0, 0, 0};

    for (int t = 0; t < NTILES; t++) {
        if (t + 1 < NTILES) {
            const char* gB = (const char*)(Bq + (size_t)(t + 1) * B_TILE_ELEMS);
            uint32_t sBn = sB0 + ((t + 1) & 1) * SMEM_B_BYTES;
            for (int i = tid; i < 2048; i += 512)
                CP_ASYNC16(sBn + i * 16, gB + i * 16);
            CP_COMMIT();
            CP_WAIT1();
        } else {
            CP_WAIT0();
        }
        __syncthreads();

        uint32_t sBt = sB0 + (t & 1) * SMEM_B_BYTES;
        float acc[2][4][4] = {};
#pragma unroll
        for (int ks = 0; ks < 8; ks++) {
            uint32_t aH[2][4], aL[2][4], bF[2][4];
            int q8 = ks * 2 + aG2;
#pragma unroll
            for (int mc = 0; mc < 2; mc++) {
                ldsm_x4(aH[mc], aBase[mc] + ((q8 ^ aXor[mc]) << 4));
                ldsm_x4(aL[mc], aBase[mc] + (((16 + q8) ^ aXor[mc]) << 4));
            }
            int qb = ks * 2 + bK8b;
#pragma unroll
            for (int p = 0; p < 2; p++)
                ldsm_x4(bF[p], sBt + bOff[p] + ((qb ^ bXor[p]) << 4));
#pragma unroll
            for (int mc = 0; mc < 2; mc++)
#pragma unroll
                for (int c = 0; c < 4; c++) {
                    mma16816h(acc[mc][c], aH[mc], &bF[c >> 1][(c & 1) * 2]);
                    mma16816h(acc[mc][c], aL[mc], &bF[c >> 1][(c & 1) * 2]);
                }
        }

        // epilogue: distances + best/second tracking
        int colbase = t * TILE_N + wn * 32;
#pragma unroll
        for (int c = 0; c < 4; c++) {
            int col0 = colbase + c * 8 + tg * 2;
            float e0 = __ldg(en + col0), e1 = __ldg(en + col0 + 1);
#pragma unroll
            for (int mc = 0; mc < 2; mc++) {
                float d0 = fmaf(-2.0f, acc[mc][c][0], e0);
                float d1 = fmaf(-2.0f, acc[mc][c][1], e1);
                float d2 = fmaf(-2.0f, acc[mc][c][2], e0);
                float d3 = fmaf(-2.0f, acc[mc][c][3], e1);
                int s0 = mc * 2, s1 = mc * 2 + 1;
                if (d0 < bd[s0]) { sd[s0] = bd[s0]; bd[s0] = d0; bc[s0] = col0; }
                else if (d0 < sd[s0]) sd[s0] = d0;
                if (d1 < bd[s0]) { sd[s0] = bd[s0]; bd[s0] = d1; bc[s0] = col0 + 1; }
                else if (d1 < sd[s0]) sd[s0] = d1;
                if (d2 < bd[s1]) { sd[s1] = bd[s1]; bd[s1] = d2; bc[s1] = col0; }
                else if (d2 < sd[s1]) sd[s1] = d2;
                if (d3 < bd[s1]) { sd[s1] = bd[s1]; bd[s1] = d3; bc[s1] = col0 + 1; }
                else if (d3 < sd[s1]) sd[s1] = d3;
            }
        }
        __syncthreads();
    }

    // merge across the 4 lanes (tg) sharing each row
#pragma unroll
    for (int s = 0; s < 4; s++) {
        unsigned long long key =
            ((unsigned long long)f2ord(bd[s]) << 32) | (unsigned)bc[s];
        float bf = bd[s], sf = sd[s];
#pragma unroll
        for (int off = 1; off <= 2; off <<= 1) {
            unsigned long long ok = __shfl_xor_sync(0xffffffffu, key, off);
            float os = __shfl_xor_sync(0xffffffffu, sf, off);
            float ob = ord2f((unsigned)(ok >> 32));
            sf = fminf(fmaxf(bf, ob), fminf(sf, os));
            bf = fminf(bf, ob);
            if (ok < key) key = ok;
        }
        if (tg == 0) {
            int row = wm * 32 + (s >> 1) * 16 + (s & 1) * 8 + g;
            skey[wn][row] = key;
            ssec[wn][row] = sf;
        }
    }
    __syncthreads();
    if (tid < 128) {
        unsigned long long km = ~0ULL;
        float b1 = 1e30f, b2 = 1e30f, smin = 1e30f;
#pragma unroll
        for (int i = 0; i < 4; i++) {
            unsigned long long ki = skey[i][tid];
            float bi = ord2f((unsigned)(ki >> 32));
            if (ki < km) km = ki;
            if (bi < b1) { b2 = b1; b1 = bi; }
            else if (bi < b2) b2 = bi;
            smin = fminf(smin, ssec[i][tid]);
        }
        float sec = fminf(b2, smin);
        int row = blockIdx.x * 128 + tid;
        g_bestidx[row] = (int)(km & 0xFFFFFFFFu);
        g_flag[row] = (sec - b1) < VQ_MARGIN ? 1 : 0;
    }
}

// exact fp32 re-scan for margin-flagged rows (rare)
__global__ void k_vq_exact(const float* __restrict__ cb, const float* __restrict__ en) {
    int row = blockIdx.x;
    if (!g_flag[row]) return;
    __shared__ float r[HD2];
    __shared__ unsigned long long red[128];
    int t = threadIdx.x;
    if (t < HD2) r[t] = g_res[(size_t)row * HD2 + t];
    __syncthreads();
    unsigned long long best = ~0ULL;
    for (int c = t; c < KC; c += 128) {
        const float4* e4 = (const float4*)(cb + (size_t)c * HD2);
        float dot = 0.0f;
#pragma unroll 8
        for (int i = 0; i < HD2 / 4; i++) {
            float4 v = e4[i];
            dot += r[4 * i] * v.x + r[4 * i + 1] * v.y + r[4 * i + 2] * v.z + r[4 * i + 3] * v.w;
        }
        float d = en[c] - 2.0f * dot;
        unsigned long long key = ((unsigned long long)f2ord(d) << 32) | (unsigned)c;
        best = min(best, key);
    }
    red[t] = best;
    __syncthreads();
#pragma unroll
    for (int o = 64; o > 0; o >>= 1) {
        if (t < o) red[t] = min(red[t], red[t + o]);
        __syncthreads();
    }
    if (t == 0) g_bestidx[row] = (int)(red[0] & 0xFFFFFFFFu);
}

__global__ void k_vq_update(const float* __restrict__ cb,
                            float* __restrict__ out_ids, int q, int first) {
    int row = blockIdx.x, d = threadIdx.x;
    int idx = g_bestidx[row];
    float e = cb[(size_t)idx * HD2 + d];
    size_t off = (size_t)row * HD2 + d;
    float r = g_res[off];
    float diff = r - e;
    if (first) g_qsum[off] = e;
    else g_qsum[off] += e;
    g_res[off] = diff;

    __shared__ float s[128];
    s[d] = diff * diff;
    __syncthreads();
#pragma unroll
    for (int o = 64; o > 0; o >>= 1) {
        if (d < o) s[d] += s[d + o];
        __syncthreads();
    }
    if (d == 0) {
        if (first) g_vqrow[row] = s[0];
        else g_vqrow[row] += s[0];
        out_ids[(size_t)row * NQ + q] = (float)idx;
    }
}

__global__ void k_recon_part(const float* __restrict__ recon) {
    float s = 0.0f;
    int n = B_ * DIN;
    for (int i = blockIdx.x * blockDim.x + threadIdx.x; i < n;
         i += gridDim.x * blockDim.x) {
        float d = recon[i] - g_xn[i];
        s += d * d;
    }
    s = blockReduce256(s);
    if (threadIdx.x == 0) g_p1[blockIdx.x] = s;
}

__global__ void k_vq_part() {
    float s = 0.0f;
    for (int i = blockIdx.x * blockDim.x + threadIdx.x; i < B_;
         i += gridDim.x * blockDim.x)
        s += g_vqrow[i];
    s = blockReduce256(s);
    if (threadIdx.x == 0) g_p2[blockIdx.x] = s;
}

__global__ void k_final(float* __restrict__ out) {
    float s1 = 0.0f;
    for (int i = threadIdx.x; i < 2048; i += 256) s1 += g_p1[i];
    s1 = blockReduce256(s1);
    float s2 = 0.0f;
    for (int i = threadIdx.x; i < 64; i += 256) s2 += g_p2[i];
    s2 = blockReduce256(s2);
    if (threadIdx.x == 0) {
        out[0] = s1 / (float)((size_t)B_ * DIN);
        out[1] = 1.25f * s2 / (float)((size_t)B_ * HD2);
    }
}

// ---------------- launch ----------------
extern "C" void kernel_launch(void* const* d_in, const int* in_sizes, int n_in,
                              void* d_out, int out_size) {
    const float* x        = (const float*)d_in[0];
    const float* emb_mean = (const float*)d_in[1];
    const float* emb_std  = (const float*)d_in[2];
    const float* enc_w0   = (const float*)d_in[3];
    const float* enc_b0   = (const float*)d_in[4];
    const float* enc_g0   = (const float*)d_in[5];
    const float* enc_w1   = (const float*)d_in[6];
    const float* enc_b1   = (const float*)d_in[7];
    const float* enc_g1   = (const float*)d_in[8];
    const float* enc_w2   = (const float*)d_in[9];
    const float* enc_b2   = (const float*)d_in[10];
    const float* enc_g2   = (const float*)d_in[11];
    const float* cbs      = (const float*)d_in[12];
    const float* dec_w0   = (const float*)d_in[13];
    const float* dec_b0   = (const float*)d_in[14];
    const float* dec_g0   = (const float*)d_in[15];
    const float* dec_w1   = (const float*)d_in[16];
    const float* dec_b1   = (const float*)d_in[17];
    const float* dec_g1   = (const float*)d_in[18];
    const float* dec_w2   = (const float*)d_in[19];
    const float* dec_b2   = (const float*)d_in[20];

    float* out       = (float*)d_out;
    float* out_recon = out;
    float* out_ids   = out + (size_t)B_ * DIN;
    float* out_loss  = out_ids + (size_t)B_ * NQ;

    cudaFuncSetAttribute(k_vq_mma, cudaFuncAttributeMaxDynamicSharedMemorySize,
                         SMEM_VQ);

    float *p_xn, *p_a, *p_b, *p_h, *p_qsum, *p_en;
    void *pv_resA, *pv_cbB;
    cudaGetSymbolAddress((void**)&p_xn, g_xn);
    cudaGetSymbolAddress((void**)&p_a, g_a);
    cudaGetSymbolAddress((void**)&p_b, g_b);
    cudaGetSymbolAddress((void**)&p_h, g_h);
    cudaGetSymbolAddress((void**)&p_qsum, g_qsum);
    cudaGetSymbolAddress((void**)&p_en, g_enorm);
    cudaGetSymbolAddress(&pv_resA, g_resA);
    cudaGetSymbolAddress(&pv_cbB, g_cbB);
    const __half* p_resA = (const __half*)pv_resA;
    const __half* p_cbB  = (const __half*)pv_cbB;

    k_normalize<<<4096, 256>>>(x, emb_mean, emb_std);

    // codebook prep (independent of encoder)
    k_enorm<<<(NQ * KC) / 256, 256>>>(cbs);
    k_prepB<<<(NQ * KC * 128) / 256, 256>>>(cbs);

    // encoder
    k_gemm<true><<<dim3(HD0 / 64, B_ / 64), 256>>>(p_xn, enc_w0, enc_b0, p_a, HD0, DIN);
    k_rmsnorm<<<B_, 256>>>(p_a, enc_g0, HD0);
    k_gemm<true><<<dim3(HD1 / 64, B_ / 64), 256>>>(p_a, enc_w1, enc_b1, p_b, HD1, HD0);
    k_rmsnorm<<<B_, 256>>>(p_b, enc_g1, HD1);
    k_gemm<true><<<dim3(HD2 / 64, B_ / 64), 256>>>(p_b, enc_w2, enc_b2, p_h, HD2, HD1);
    k_rmsnorm<<<B_, 256>>>(p_h, enc_g2, HD2);

    // residual VQ (fp16 2-term HMMA + margin-guarded exact fallback)
    k_copy_res<<<2048, 256>>>();
    for (int q = 0; q < NQ; q++) {
        const float* cbq = cbs + (size_t)q * KC * HD2;
        k_prepA<<<(B_ * 256) / 256, 256>>>();
        k_vq_mma<<<B_ / 128, 512, SMEM_VQ>>>(p_resA, p_cbB + (size_t)q * KC * 128,
                                             p_en + (size_t)q * KC);
        k_vq_exact<<<B_, 128>>>(cbq, p_en + (size_t)q * KC);
        k_vq_update<<<B_, 128>>>(cbq, out_ids, q, q == 0 ? 1 : 0);
    }

    // decoder
    k_gemm<true><<<dim3(HD1 / 64, B_ / 64), 256>>>(p_qsum, dec_w0, dec_b0, p_b, HD1, HD2);
    k_rmsnorm<<<B_, 256>>>(p_b, dec_g0, HD1);
    k_gemm<true><<<dim3(HD0 / 64, B_ / 64), 256>>>(p_b, dec_w1, dec_b1, p_a, HD0, HD1);
    k_rmsnorm<<<B_, 256>>>(p_a, dec_g1, HD0);
    k_gemm<false><<<dim3(DIN / 64, B_ / 64), 256>>>(p_a, dec_w2, dec_b2, out_recon, DIN, HD0);

    k_recon_part<<<2048, 256>>>(out_recon);
    k_vq_part<<<64, 256>>>();
    k_final<<<1, 256>>>(out_loss);
}

// round 5
// speedup vs baseline: 1.6774x; 1.0911x over previous
#include <cuda_runtime.h>
#include <cuda_bf16.h>
#include <cuda_fp16.h>
#include <stdint.h>

// ---------------- problem constants ----------------
#define B_    16384
#define DIN   768
#define HD0   512
#define HD1   256
#define HD2   128
#define NQ    4
#define KC    8192
#define EPS_  1e-6f

// VQ geometry: fp16 2-term A'=[hi|lo] (256 halves/row), B'=e_hi (128 halves/code)
// CTA: 256 thr, 128 rows x 4096 codes (half codebook). Grid 256 = 128 rb x 2 split.
#define TILE_N  64
#define TILES_PER_SPLIT 64               // 4096 / 64
#define A_BLK_ELEMS (128 * 256)          // 32768 halves = 64KB
#define B_TILE_ELEMS (TILE_N * 128)      // 8192 halves = 16KB
#define SMEM_A_BYTES 65536
#define SMEM_B_BYTES 16384
#define SMEM_VQ (SMEM_A_BYTES + 2 * SMEM_B_BYTES)  // 98304
#define VQ_MARGIN 2e-3f

// ---------------- scratch ----------------
__device__ float g_xn[B_ * DIN];
__device__ float g_a[B_ * HD0];
__device__ float g_b[B_ * HD1];
__device__ float g_h[B_ * HD2];
__device__ float g_res[B_ * HD2];
__device__ float g_qsum[B_ * HD2];
__device__ float g_enorm[NQ * KC];
__device__ int   g_bestidx[B_];
__device__ int   g_flag[B_];
__device__ float g_vqrow[B_];
__device__ float g_p1[2048];
__device__ float g_p2[64];
__device__ __half g_resA[B_ * 256];            // A' blocks, pre-swizzled
__device__ __half g_cbB[NQ * KC * 128];        // B' tiles, pre-swizzled
__device__ unsigned long long g_pkey[2 * B_];  // per-split best key
__device__ float g_psec[2 * B_];               // per-split second-best dist

// ---------------- PTX helpers ----------------
__device__ __forceinline__ uint32_t smem_u32(const void* p) {
    uint32_t a;
    asm("{ .reg .u64 t; cvta.to.shared.u64 t, %1; cvt.u32.u64 %0, t; }" : "=r"(a) : "l"(p));
    return a;
}
#define CP_ASYNC16(dst, src) \
    asm volatile("cp.async.cg.shared.global [%0], [%1], 16;" :: "r"(dst), "l"(src))
#define CP_COMMIT() asm volatile("cp.async.commit_group;" ::: "memory")
#define CP_WAIT0()  asm volatile("cp.async.wait_group 0;" ::: "memory")
#define CP_WAIT1()  asm volatile("cp.async.wait_group 1;" ::: "memory")

__device__ __forceinline__ void ldsm_x4(uint32_t* r, uint32_t addr) {
    asm volatile("ldmatrix.sync.aligned.m8n8.x4.shared.b16 {%0,%1,%2,%3}, [%4];"
                 : "=r"(r[0]), "=r"(r[1]), "=r"(r[2]), "=r"(r[3]) : "r"(addr));
}
__device__ __forceinline__ void mma16816h(float* c, const uint32_t* a, const uint32_t* b) {
    asm volatile(
        "mma.sync.aligned.m16n8k16.row.col.f32.f16.f16.f32 "
        "{%0,%1,%2,%3}, {%4,%5,%6,%7}, {%8,%9}, {%0,%1,%2,%3};"
        : "+f"(c[0]), "+f"(c[1]), "+f"(c[2]), "+f"(c[3])
        : "r"(a[0]), "r"(a[1]), "r"(a[2]), "r"(a[3]), "r"(b[0]), "r"(b[1]));
}

__device__ __forceinline__ unsigned f2ord(float f) {
    unsigned u = __float_as_uint(f);
    return u ^ (((unsigned)((int)u >> 31)) | 0x80000000u);
}
__device__ __forceinline__ float ord2f(unsigned u) {
    u ^= (u & 0x80000000u) ? 0x80000000u : 0xFFFFFFFFu;
    return __uint_as_float(u);
}

// write one residual element into the swizzled fp16 hi/lo A' layout
__device__ __forceinline__ void writeA(int row, int k, float x) {
    __half hi = __float2half(x);
    __half lo = __float2half(x - __half2float(hi));
    int m = row & 127, rb = row >> 7;
    int q8 = k >> 3, b = (k & 7) * 2;
    int off_hi = m * 512 + ((q8 ^ (m & 7)) << 4) + b;
    int off_lo = m * 512 + (((16 + q8) ^ (m & 7)) << 4) + b;
    __half* base = g_resA + (size_t)rb * A_BLK_ELEMS;
    base[off_hi >> 1] = hi;
    base[off_lo >> 1] = lo;
}

// ---------------- small helpers ----------------
__device__ __forceinline__ float blockReduce256(float v) {
    __shared__ float red[32];
    int lane = threadIdx.x & 31, w = threadIdx.x >> 5;
#pragma unroll
    for (int o = 16; o > 0; o >>= 1) v += __shfl_down_sync(0xffffffffu, v, o);
    __syncthreads();
    if (lane == 0) red[w] = v;
    __syncthreads();
    if (threadIdx.x == 0) {
        float t = 0.0f;
        int nw = (blockDim.x + 31) >> 5;
        for (int i = 0; i < nw; i++) t += red[i];
        red[0] = t;
    }
    __syncthreads();
    return red[0];
}

// ---------------- elementwise / MLP kernels (proven) ----------------
__global__ void k_normalize(const float* __restrict__ x,
                            const float* __restrict__ mean,
                            const float* __restrict__ stdv) {
    int n = B_ * DIN;
    for (int i = blockIdx.x * blockDim.x + threadIdx.x; i < n;
         i += gridDim.x * blockDim.x) {
        int c = i % DIN;
        g_xn[i] = (x[i] - mean[c]) / stdv[c];
    }
}

template <bool RELU>
__global__ __launch_bounds__(256)
void k_gemm(const float* __restrict__ A, const float* __restrict__ W,
            const float* __restrict__ bias, float* __restrict__ C,
            int N, int K) {
    __shared__ float As[16][68];
    __shared__ float Ws[16][68];
    int m0 = blockIdx.y * 64, n0 = blockIdx.x * 64;
    int tid = threadIdx.x;
    int ty = tid >> 4, tx = tid & 15;
    int arow = tid >> 2, acol = (tid & 3) * 4;
    int wrow = tid >> 4, wcol = (tid & 15) * 4;

    float acc[4][4] = {};
    for (int k0 = 0; k0 < K; k0 += 16) {
        float4 av = *(const float4*)&A[(size_t)(m0 + arow) * K + k0 + acol];
        As[acol + 0][arow] = av.x;
        As[acol + 1][arow] = av.y;
        As[acol + 2][arow] = av.z;
        As[acol + 3][arow] = av.w;
        *(float4*)&Ws[wrow][wcol] =
            *(const float4*)&W[(size_t)(k0 + wrow) * N + n0 + wcol];
        __syncthreads();
#pragma unroll
        for (int k = 0; k < 16; k++) {
            float4 a4 = *(const float4*)&As[k][ty * 4];
            float4 w4 = *(const float4*)&Ws[k][tx * 4];
            float ar[4] = {a4.x, a4.y, a4.z, a4.w};
            float wr[4] = {w4.x, w4.y, w4.z, w4.w};
#pragma unroll
            for (int i = 0; i < 4; i++)
#pragma unroll
                for (int j = 0; j < 4; j++) acc[i][j] += ar[i] * wr[j];
        }
        __syncthreads();
    }
#pragma unroll
    for (int j = 0; j < 4; j++) {
        float bj = bias[n0 + tx * 4 + j];
#pragma unroll
        for (int i = 0; i < 4; i++) {
            float v = acc[i][j] + bj;
            if (RELU) v = fmaxf(v, 0.0f);
            C[(size_t)(m0 + ty * 4 + i) * N + n0 + tx * 4 + j] = v;
        }
    }
}

__global__ void k_rmsnorm(float* __restrict__ X, const float* __restrict__ g, int N) {
    int row = blockIdx.x;
    float* xr = X + (size_t)row * N;
    float s = 0.0f;
    for (int n = threadIdx.x; n < N; n += blockDim.x) {
        float v = xr[n];
        s += v * v;
    }
    s = blockReduce256(s);
    float scale = rsqrtf(s / (float)N + EPS_);
    for (int n = threadIdx.x; n < N; n += blockDim.x)
        xr[n] = xr[n] * scale * g[n];
}

__global__ void k_enorm(const float* __restrict__ cb) {
    int c = blockIdx.x * blockDim.x + threadIdx.x;
    if (c < NQ * KC) {
        const float4* p = (const float4*)(cb + (size_t)c * HD2);
        float s = 0.0f;
#pragma unroll 8
        for (int i = 0; i < HD2 / 4; i++) {
            float4 v = p[i];
            s += v.x * v.x + v.y * v.y + v.z * v.z + v.w * v.w;
        }
        g_enorm[c] = s;
    }
}

// residual init: res = h, plus swizzled A' hi/lo
__global__ void k_res_init() {
    int idx = blockIdx.x * blockDim.x + threadIdx.x;
    if (idx >= B_ * HD2) return;
    int row = idx >> 7, k = idx & 127;
    float x = g_h[idx];
    g_res[idx] = x;
    writeA(row, k, x);
}

// B' tile prep: tile = 64 codes x 128 halves (hi only), swizzled
__global__ void k_prepB(const float* __restrict__ cb) {
    int idx = blockIdx.x * blockDim.x + threadIdx.x;
    if (idx >= NQ * KC * 128) return;
    int k = idx & 127;
    int qc = idx >> 7;
    int c = qc & (KC - 1), q = qc >> 13;
    __half v = __float2half(cb[(size_t)qc * HD2 + k]);
    int tile = c >> 6, n = c & 63;
    int byte = n * 256 + ((((k >> 3) ^ (n & 7))) << 4) + (k & 7) * 2;
    g_cbB[(size_t)q * (KC * 128) + tile * B_TILE_ELEMS + (byte >> 1)] = v;
}

// ---------------- fused VQ score GEMM + argmin (fp16 HMMA, 2 CTA/SM) ----------------
// CTA: 8 warps (4m x 2n), 128 rows x 4096 codes; A resident, B double-buffered.
__global__ __launch_bounds__(256, 2)
void k_vq_mma(const __half* __restrict__ Ablk,
              const __half* __restrict__ Bq,
              const float* __restrict__ en_q) {
    extern __shared__ char smem[];
    uint32_t sA = smem_u32(smem);
    uint32_t sB0 = sA + SMEM_A_BYTES;
    __shared__ unsigned long long skey[2][128];
    __shared__ float ssec[2][128];

    int tid = threadIdx.x, lid = tid & 31, wid = tid >> 5;
    int rb = blockIdx.x & 127, split = blockIdx.x >> 7;
    int wm = wid >> 1, wn = wid & 1;     // warp grid 4(m) x 2(n)
    int tg = lid & 3, g = lid >> 2;
    int grp = lid >> 3, sub = lid & 7;

    const __half* Bs = Bq + (size_t)split * 4096 * 128;
    const float* en = en_q + split * 4096;

    // stage A block (64KB, 16 quads/thread)
    const char* gA = (const char*)(Ablk + (size_t)rb * A_BLK_ELEMS);
    for (int i = tid; i < 4096; i += 256)
        CP_ASYNC16(sA + i * 16, gA + i * 16);
    // prefetch B tile 0 (16KB, 4 quads/thread)
    {
        const char* gB = (const char*)Bs;
        for (int i = tid; i < 1024; i += 256)
            CP_ASYNC16(sB0 + i * 16, gB + i * 16);
    }
    CP_COMMIT();

    // ldmatrix lane-address invariants
    uint32_t aBase[2]; int aXor[2];
    int aG2 = grp >> 1;
#pragma unroll
    for (int mc = 0; mc < 2; mc++) {
        int row = wm * 32 + mc * 16 + (grp & 1) * 8 + sub;
        aBase[mc] = sA + row * 512;
        aXor[mc] = row & 7;
    }
    uint32_t bOff[2]; int bXor[2];
    int bK8b = grp & 1;
#pragma unroll
    for (int p = 0; p < 2; p++) {
        int n = wn * 32 + p * 16 + (grp >> 1) * 8 + sub;
        bOff[p] = n * 256;
        bXor[p] = n & 7;
    }

    float bd[4] = {1e30f, 1e30f, 1e30f, 1e30f};
    float sd[4] = {1e30f, 1e30f, 1e30f, 1e30f};
    int bc[4] = {0, 0, 0, 0};

    for (int t = 0; t < TILES_PER_SPLIT; t++) {
        if (t + 1 < TILES_PER_SPLIT) {
            const char* gB = (const char*)(Bs + (size_t)(t + 1) * B_TILE_ELEMS);
            uint32_t sBn = sB0 + ((t + 1) & 1) * SMEM_B_BYTES;
            for (int i = tid; i < 1024; i += 256)
                CP_ASYNC16(sBn + i * 16, gB + i * 16);
            CP_COMMIT();
            CP_WAIT1();
        } else {
            CP_WAIT0();
        }
        __syncthreads();

        uint32_t sBt = sB0 + (t & 1) * SMEM_B_BYTES;
        float acc[2][4][4] = {};
#pragma unroll
        for (int ks = 0; ks < 8; ks++) {
            uint32_t bF[2][4];
            int qb = ks * 2 + bK8b;
#pragma unroll
            for (int p = 0; p < 2; p++)
                ldsm_x4(bF[p], sBt + bOff[p] + ((qb ^ bXor[p]) << 4));
            int q8 = ks * 2 + aG2;
            {
                uint32_t aH[2][4];
#pragma unroll
                for (int mc = 0; mc < 2; mc++)
                    ldsm_x4(aH[mc], aBase[mc] + ((q8 ^ aXor[mc]) << 4));
#pragma unroll
                for (int mc = 0; mc < 2; mc++)
#pragma unroll
                    for (int c = 0; c < 4; c++)
                        mma16816h(acc[mc][c], aH[mc], &bF[c >> 1][(c & 1) * 2]);
            }
            {
                uint32_t aL[2][4];
#pragma unroll
                for (int mc = 0; mc < 2; mc++)
                    ldsm_x4(aL[mc], aBase[mc] + (((16 + q8) ^ aXor[mc]) << 4));
#pragma unroll
                for (int mc = 0; mc < 2; mc++)
#pragma unroll
                    for (int c = 0; c < 4; c++)
                        mma16816h(acc[mc][c], aL[mc], &bF[c >> 1][(c & 1) * 2]);
            }
        }

        // epilogue: distances + best/second tracking
        int colbase = split * 4096 + t * TILE_N + wn * 32;
#pragma unroll
        for (int c = 0; c < 4; c++) {
            int col0 = colbase + c * 8 + tg * 2;
            float e0 = __ldg(en_q + col0), e1 = __ldg(en_q + col0 + 1);
#pragma unroll
            for (int mc = 0; mc < 2; mc++) {
                float d0 = fmaf(-2.0f, acc[mc][c][0], e0);
                float d1 = fmaf(-2.0f, acc[mc][c][1], e1);
                float d2 = fmaf(-2.0f, acc[mc][c][2], e0);
                float d3 = fmaf(-2.0f, acc[mc][c][3], e1);
                int s0 = mc * 2, s1 = mc * 2 + 1;
                if (d0 < bd[s0]) { sd[s0] = bd[s0]; bd[s0] = d0; bc[s0] = col0; }
                else if (d0 < sd[s0]) sd[s0] = d0;
                if (d1 < bd[s0]) { sd[s0] = bd[s0]; bd[s0] = d1; bc[s0] = col0 + 1; }
                else if (d1 < sd[s0]) sd[s0] = d1;
                if (d2 < bd[s1]) { sd[s1] = bd[s1]; bd[s1] = d2; bc[s1] = col0; }
                else if (d2 < sd[s1]) sd[s1] = d2;
                if (d3 < bd[s1]) { sd[s1] = bd[s1]; bd[s1] = d3; bc[s1] = col0 + 1; }
                else if (d3 < sd[s1]) sd[s1] = d3;
            }
        }
        __syncthreads();
    }

    // merge across the 4 lanes (tg) sharing each row
#pragma unroll
    for (int s = 0; s < 4; s++) {
        unsigned long long key =
            ((unsigned long long)f2ord(bd[s]) << 32) | (unsigned)bc[s];
        float bf = bd[s], sf = sd[s];
#pragma unroll
        for (int off = 1; off <= 2; off <<= 1) {
            unsigned long long ok = __shfl_xor_sync(0xffffffffu, key, off);
            float os = __shfl_xor_sync(0xffffffffu, sf, off);
            float ob = ord2f((unsigned)(ok >> 32));
            sf = fminf(fmaxf(bf, ob), fminf(sf, os));
            bf = fminf(bf, ob);
            if (ok < key) key = ok;
        }
        if (tg == 0) {
            int row = wm * 32 + (s >> 1) * 16 + (s & 1) * 8 + g;
            skey[wn][row] = key;
            ssec[wn][row] = sf;
        }
    }
    __syncthreads();
    if (tid < 128) {
        unsigned long long k0 = skey[0][tid], k1 = skey[1][tid];
        float b0 = ord2f((unsigned)(k0 >> 32)), b1 = ord2f((unsigned)(k1 >> 32));
        float sec = fminf(fmaxf(b0, b1), fminf(ssec[0][tid], ssec[1][tid]));
        int row = rb * 128 + tid;
        g_pkey[split * B_ + row] = min(k0, k1);
        g_psec[split * B_ + row] = sec;
    }
}

// merge the two code-splits into final bestidx + margin flag
__global__ void k_vq_merge() {
    int row = blockIdx.x * blockDim.x + threadIdx.x;
    if (row >= B_) return;
    unsigned long long k0 = g_pkey[row], k1 = g_pkey[B_ + row];
    float b0 = ord2f((unsigned)(k0 >> 32)), b1 = ord2f((unsigned)(k1 >> 32));
    float sec = fminf(fmaxf(b0, b1), fminf(g_psec[row], g_psec[B_ + row]));
    unsigned long long km = min(k0, k1);
    float best = ord2f((unsigned)(km >> 32));
    g_bestidx[row] = (int)(km & 0xFFFFFFFFu);
    g_flag[row] = (sec - best) < VQ_MARGIN ? 1 : 0;
}

// exact fp32 re-scan for margin-flagged rows (rare)
__global__ void k_vq_exact(const float* __restrict__ cb, const float* __restrict__ en) {
    int row = blockIdx.x;
    if (!g_flag[row]) return;
    __shared__ float r[HD2];
    __shared__ unsigned long long red[128];
    int t = threadIdx.x;
    if (t < HD2) r[t] = g_res[(size_t)row * HD2 + t];
    __syncthreads();
    unsigned long long best = ~0ULL;
    for (int c = t; c < KC; c += 128) {
        const float4* e4 = (const float4*)(cb + (size_t)c * HD2);
        float dot = 0.0f;
#pragma unroll 8
        for (int i = 0; i < HD2 / 4; i++) {
            float4 v = e4[i];
            dot += r[4 * i] * v.x + r[4 * i + 1] * v.y + r[4 * i + 2] * v.z + r[4 * i + 3] * v.w;
        }
        float d = en[c] - 2.0f * dot;
        unsigned long long key = ((unsigned long long)f2ord(d) << 32) | (unsigned)c;
        best = min(best, key);
    }
    red[t] = best;
    __syncthreads();
#pragma unroll
    for (int o = 64; o > 0; o >>= 1) {
        if (t < o) red[t] = min(red[t], red[t + o]);
        __syncthreads();
    }
    if (t == 0) g_bestidx[row] = (int)(red[0] & 0xFFFFFFFFu);
}

// gather code, update qsum/residual/vq-loss, and write next A' in place
__global__ void k_vq_update(const float* __restrict__ cb,
                            float* __restrict__ out_ids, int q, int first) {
    int row = blockIdx.x, d = threadIdx.x;
    int idx = g_bestidx[row];
    float e = cb[(size_t)idx * HD2 + d];
    size_t off = (size_t)row * HD2 + d;
    float r = g_res[off];
    float diff = r - e;
    if (first) g_qsum[off] = e;
    else g_qsum[off] += e;
    g_res[off] = diff;
    writeA(row, d, diff);   // A' for the next quantizer

    __shared__ float s[128];
    s[d] = diff * diff;
    __syncthreads();
#pragma unroll
    for (int o = 64; o > 0; o >>= 1) {
        if (d < o) s[d] += s[d + o];
        __syncthreads();
    }
    if (d == 0) {
        if (first) g_vqrow[row] = s[0];
        else g_vqrow[row] += s[0];
        out_ids[(size_t)row * NQ + q] = (float)idx;
    }
}

__global__ void k_recon_part(const float* __restrict__ recon) {
    float s = 0.0f;
    int n = B_ * DIN;
    for (int i = blockIdx.x * blockDim.x + threadIdx.x; i < n;
         i += gridDim.x * blockDim.x) {
        float d = recon[i] - g_xn[i];
        s += d * d;
    }
    s = blockReduce256(s);
    if (threadIdx.x == 0) g_p1[blockIdx.x] = s;
}

__global__ void k_vq_part() {
    float s = 0.0f;
    for (int i = blockIdx.x * blockDim.x + threadIdx.x; i < B_;
         i += gridDim.x * blockDim.x)
        s += g_vqrow[i];
    s = blockReduce256(s);
    if (threadIdx.x == 0) g_p2[blockIdx.x] = s;
}

__global__ void k_final(float* __restrict__ out) {
    float s1 = 0.0f;
    for (int i = threadIdx.x; i < 2048; i += 256) s1 += g_p1[i];
    s1 = blockReduce256(s1);
    float s2 = 0.0f;
    for (int i = threadIdx.x; i < 64; i += 256) s2 += g_p2[i];
    s2 = blockReduce256(s2);
    if (threadIdx.x == 0) {
        out[0] = s1 / (float)((size_t)B_ * DIN);
        out[1] = 1.25f * s2 / (float)((size_t)B_ * HD2);
    }
}

// ---------------- launch ----------------
extern "C" void kernel_launch(void* const* d_in, const int* in_sizes, int n_in,
                              void* d_out, int out_size) {
    const float* x        = (const float*)d_in[0];
    const float* emb_mean = (const float*)d_in[1];
    const float* emb_std  = (const float*)d_in[2];
    const float* enc_w0   = (const float*)d_in[3];
    const float* enc_b0   = (const float*)d_in[4];
    const float* enc_g0   = (const float*)d_in[5];
    const float* enc_w1   = (const float*)d_in[6];
    const float* enc_b1   = (const float*)d_in[7];
    const float* enc_g1   = (const float*)d_in[8];
    const float* enc_w2   = (const float*)d_in[9];
    const float* enc_b2   = (const float*)d_in[10];
    const float* enc_g2   = (const float*)d_in[11];
    const float* cbs      = (const float*)d_in[12];
    const float* dec_w0   = (const float*)d_in[13];
    const float* dec_b0   = (const float*)d_in[14];
    const float* dec_g0   = (const float*)d_in[15];
    const float* dec_w1   = (const float*)d_in[16];
    const float* dec_b1   = (const float*)d_in[17];
    const float* dec_g1   = (const float*)d_in[18];
    const float* dec_w2   = (const float*)d_in[19];
    const float* dec_b2   = (const float*)d_in[20];

    float* out       = (float*)d_out;
    float* out_recon = out;
    float* out_ids   = out + (size_t)B_ * DIN;
    float* out_loss  = out_ids + (size_t)B_ * NQ;

    cudaFuncSetAttribute(k_vq_mma, cudaFuncAttributeMaxDynamicSharedMemorySize,
                         SMEM_VQ);

    float *p_xn, *p_a, *p_b, *p_h, *p_qsum, *p_en;
    void *pv_resA, *pv_cbB;
    cudaGetSymbolAddress((void**)&p_xn, g_xn);
    cudaGetSymbolAddress((void**)&p_a, g_a);
    cudaGetSymbolAddress((void**)&p_b, g_b);
    cudaGetSymbolAddress((void**)&p_h, g_h);
    cudaGetSymbolAddress((void**)&p_qsum, g_qsum);
    cudaGetSymbolAddress((void**)&p_en, g_enorm);
    cudaGetSymbolAddress(&pv_resA, g_resA);
    cudaGetSymbolAddress(&pv_cbB, g_cbB);
    const __half* p_resA = (const __half*)pv_resA;
    const __half* p_cbB  = (const __half*)pv_cbB;

    k_normalize<<<4096, 256>>>(x, emb_mean, emb_std);

    // codebook prep (independent of encoder)
    k_enorm<<<(NQ * KC) / 256, 256>>>(cbs);
    k_prepB<<<(NQ * KC * 128) / 256, 256>>>(cbs);

    // encoder
    k_gemm<true><<<dim3(HD0 / 64, B_ / 64), 256>>>(p_xn, enc_w0, enc_b0, p_a, HD0, DIN);
    k_rmsnorm<<<B_, 256>>>(p_a, enc_g0, HD0);
    k_gemm<true><<<dim3(HD1 / 64, B_ / 64), 256>>>(p_a, enc_w1, enc_b1, p_b, HD1, HD0);
    k_rmsnorm<<<B_, 256>>>(p_b, enc_g1, HD1);
    k_gemm<true><<<dim3(HD2 / 64, B_ / 64), 256>>>(p_b, enc_w2, enc_b2, p_h, HD2, HD1);
    k_rmsnorm<<<B_, 256>>>(p_h, enc_g2, HD2);

    // residual VQ (fp16 2-term HMMA, 2 CTA/SM, code-split + merge)
    k_res_init<<<(B_ * HD2) / 256, 256>>>();
    for (int q = 0; q < NQ; q++) {
        const float* cbq = cbs + (size_t)q * KC * HD2;
        k_vq_mma<<<256, 256, SMEM_VQ>>>(p_resA, p_cbB + (size_t)q * KC * 128,
                                        p_en + (size_t)q * KC);
        k_vq_merge<<<B_ / 256, 256>>>();
        k_vq_exact<<<B_, 128>>>(cbq, p_en + (size_t)q * KC);
        k_vq_update<<<B_, 128>>>(cbq, out_ids, q, q == 0 ? 1 : 0);
    }

    // decoder
    k_gemm<true><<<dim3(HD1 / 64, B_ / 64), 256>>>(p_qsum, dec_w0, dec_b0, p_b, HD1, HD2);
    k_rmsnorm<<<B_, 256>>>(p_b, dec_g0, HD1);
    k_gemm<true><<<dim3(HD0 / 64, B_ / 64), 256>>>(p_b, dec_w1, dec_b1, p_a, HD0, HD1);
    k_rmsnorm<<<B_, 256>>>(p_a, dec_g1, HD0);
    k_gemm<false><<<dim3(DIN / 64, B_ / 64), 256>>>(p_a, dec_w2, dec_b2, out_recon, DIN, HD0);

    k_recon_part<<<2048, 256>>>(out_recon);
    k_vq_part<<<64, 256>>>();
    k_final<<<1, 256>>>(out_loss);
}